// round 2
// baseline (speedup 1.0000x reference)
#include <cuda_runtime.h>

#define BB 4
#define NN 4096
#define HH 16
#define DD 64
#define HD (HH*DD)          // 1024
#define BH (BB*HH)          // 64
#define CH 8                // chunks over N for phase-1 parallelism
#define CHTOK (NN/CH)       // 512 tokens per chunk
#define EPSZ 1e-6f

// Scratch (static device globals — no allocation)
__device__ float g_KVpart[CH*BH*DD*DD];   // 8 MB: per-chunk partial K^T V
__device__ float g_KSpart[CH*BH*DD];      // per-chunk partial K column sums
__device__ float g_C[BH*DD*DD];           // folded KV @ W_out_h^T (1 MB)
__device__ float g_Ksum[BH*DD];           // reduced K sums

__device__ __forceinline__ float phi(float x) {
    // elu(x)+1 : x>0 ? x+1 : exp(x)
    return x > 0.0f ? x + 1.0f : __expf(x);
}
__device__ __forceinline__ float4 phi4(float4 v) {
    float4 r; r.x = phi(v.x); r.y = phi(v.y); r.z = phi(v.z); r.w = phi(v.w);
    return r;
}

// ---------------------------------------------------------------------------
// Phase 1: per-(b,h,chunk) partial KV[d][m] = sum_t phi(K[t][d]) * V[t][m]
// 512 blocks, 256 threads, 4x4 register blocking over a 64x64 output.
// ---------------------------------------------------------------------------
__global__ __launch_bounds__(256) void kv_partial_kernel(
    const float* __restrict__ key, const float* __restrict__ value)
{
    __shared__ float Ks[32][68];
    __shared__ float Vs[32][68];

    const int bx  = blockIdx.x;       // 0 .. BH*CH-1
    const int c   = bx % CH;
    const int bh  = bx / CH;
    const int b   = bh / HH;
    const int h   = bh % HH;
    const int tid = threadIdx.x;
    const int ty  = tid >> 4;         // 0..15  (d block)
    const int tx  = tid & 15;         // 0..15  (m block)

    float acc[4][4];
#pragma unroll
    for (int i = 0; i < 4; i++)
#pragma unroll
        for (int j = 0; j < 4; j++) acc[i][j] = 0.0f;
    float ksacc = 0.0f;

    const int n0 = c * CHTOK;

    for (int tile = 0; tile < CHTOK / 32; tile++) {
        const int t0 = n0 + tile * 32;
        // cooperative load: 32 tokens x 64 floats for K (phi applied) and V
#pragma unroll
        for (int i = 0; i < 2; i++) {
            const int lin = tid + i * 256;      // 0..511
            const int t   = lin >> 4;           // 0..31
            const int d4  = (lin & 15) * 4;
            const int row = (b * NN + t0 + t);
            const float4 kq = *(const float4*)(key   + (size_t)row * HD + h * DD + d4);
            const float4 vq = *(const float4*)(value + (size_t)row * HD + h * DD + d4);
            *(float4*)&Ks[t][d4] = phi4(kq);
            *(float4*)&Vs[t][d4] = vq;
        }
        __syncthreads();

        if (tid < 64) {
#pragma unroll
            for (int t = 0; t < 32; t++) ksacc += Ks[t][tid];
        }

#pragma unroll 4
        for (int t = 0; t < 32; t++) {
            const float4 av = *(const float4*)&Ks[t][ty * 4];
            const float4 vv = *(const float4*)&Vs[t][tx * 4];
            float a[4] = {av.x, av.y, av.z, av.w};
            float v[4] = {vv.x, vv.y, vv.z, vv.w};
#pragma unroll
            for (int i = 0; i < 4; i++)
#pragma unroll
                for (int j = 0; j < 4; j++) acc[i][j] += a[i] * v[j];
        }
        __syncthreads();
    }

    float* outp = g_KVpart + (size_t)(c * BH + bh) * DD * DD;
#pragma unroll
    for (int i = 0; i < 4; i++) {
        float4 w = make_float4(acc[i][0], acc[i][1], acc[i][2], acc[i][3]);
        *(float4*)(outp + (ty * 4 + i) * DD + tx * 4) = w;
    }
    if (tid < 64) g_KSpart[(c * BH + bh) * DD + tid] = ksacc;
}

// ---------------------------------------------------------------------------
// Phase 1.5: reduce chunk partials; fold projection:
//   C[bh][d][j] = sum_m KV[bh][d][m] * W_out[j][h*64+m]
// 64 blocks, 256 threads.
// ---------------------------------------------------------------------------
__global__ __launch_bounds__(256) void fold_kernel(const float* __restrict__ W_out)
{
    __shared__ float KVs[DD][68];
    __shared__ float Ws[DD][68];

    const int bh  = blockIdx.x;
    const int h   = bh % HH;
    const int tid = threadIdx.x;
    const int ty  = tid >> 4;
    const int tx  = tid & 15;

    // reduce KV partials into smem
#pragma unroll
    for (int i = 0; i < 4; i++) {
        const int lin = (tid + i * 256) * 4;    // float4 element offset, 0..4092
        float4 s = make_float4(0.f, 0.f, 0.f, 0.f);
#pragma unroll
        for (int cc = 0; cc < CH; cc++) {
            const float4 p = *(const float4*)(g_KVpart + (size_t)(cc * BH + bh) * DD * DD + lin);
            s.x += p.x; s.y += p.y; s.z += p.z; s.w += p.w;
        }
        const int d = lin >> 6, m = lin & 63;
        *(float4*)&KVs[d][m] = s;
    }
    // load W slice: Ws[j][m] = W_out[j*HD + h*64 + m]
#pragma unroll
    for (int i = 0; i < 4; i++) {
        const int lin = (tid + i * 256) * 4;
        const int j = lin >> 6, m = lin & 63;
        *(float4*)&Ws[j][m] = *(const float4*)(W_out + (size_t)j * HD + h * DD + m);
    }
    if (tid < 64) {
        float s = 0.0f;
#pragma unroll
        for (int cc = 0; cc < CH; cc++) s += g_KSpart[(cc * BH + bh) * DD + tid];
        g_Ksum[bh * DD + tid] = s;
    }
    __syncthreads();

    float acc[4][4];
#pragma unroll
    for (int i = 0; i < 4; i++)
#pragma unroll
        for (int j = 0; j < 4; j++) acc[i][j] = 0.0f;

#pragma unroll 4
    for (int m = 0; m < 64; m++) {
        float a[4], w[4];
#pragma unroll
        for (int i = 0; i < 4; i++) a[i] = KVs[ty * 4 + i][m];
#pragma unroll
        for (int j = 0; j < 4; j++) w[j] = Ws[tx * 4 + j][m];
#pragma unroll
        for (int i = 0; i < 4; i++)
#pragma unroll
            for (int j = 0; j < 4; j++) acc[i][j] += a[i] * w[j];
    }

    float* cp = g_C + (size_t)bh * DD * DD;
#pragma unroll
    for (int i = 0; i < 4; i++) {
        float4 w = make_float4(acc[i][0], acc[i][1], acc[i][2], acc[i][3]);
        *(float4*)(cp + (ty * 4 + i) * DD + tx * 4) = w;
    }
}

// ---------------------------------------------------------------------------
// Phase 2: per 64-token tile, accumulate over heads:
//   out[t][j] = b_out[j] + sum_h Z[t,h] * (Qphi[t,h,:] @ C[b,h][:,j])
// Z folded into Qphi rows before the matmul. 256 blocks, 256 threads.
// ---------------------------------------------------------------------------
__global__ __launch_bounds__(256) void out_kernel(
    const float* __restrict__ query, const float* __restrict__ b_out,
    float* __restrict__ out)
{
    __shared__ float Qp[64][68];
    __shared__ float Cs[64][68];
    __shared__ float Ksum_s[DD];

    const int blk = blockIdx.x;                 // 0 .. B*N/64 - 1
    const int b   = blk / (NN / 64);
    const int t0g = blk * 64;                   // global token row start
    const int tid = threadIdx.x;
    const int ty  = tid >> 4;
    const int tx  = tid & 15;

    float acc[4][4];
#pragma unroll
    for (int i = 0; i < 4; i++)
#pragma unroll
        for (int j = 0; j < 4; j++) acc[i][j] = 0.0f;

    for (int h = 0; h < HH; h++) {
        const int bh = b * HH + h;
        if (tid < 64) Ksum_s[tid] = g_Ksum[bh * DD + tid];

        // load Q tile with phi
#pragma unroll
        for (int i = 0; i < 4; i++) {
            const int lin = tid + i * 256;      // 0..1023
            const int t = lin >> 4;
            const int d4 = (lin & 15) * 4;
            const float4 qv = *(const float4*)(query + (size_t)(t0g + t) * HD + h * DD + d4);
            *(float4*)&Qp[t][d4] = phi4(qv);
        }
        // load C tile
#pragma unroll
        for (int i = 0; i < 4; i++) {
            const int lin = tid + i * 256;
            const int t = lin >> 4;
            const int d4 = (lin & 15) * 4;
            *(float4*)&Cs[t][d4] = *(const float4*)(g_C + (size_t)bh * DD * DD + lin * 4);
        }
        __syncthreads();

        // Z and row scaling (64 threads, one token each)
        if (tid < 64) {
            float dot = 0.0f;
#pragma unroll
            for (int d = 0; d < 64; d++) dot += Qp[tid][d] * Ksum_s[d];
            const float z = 1.0f / (dot + EPSZ);
#pragma unroll
            for (int d = 0; d < 64; d++) Qp[tid][d] *= z;
        }
        __syncthreads();

        // acc += Qp(64x64) @ Cs(64x64), 4x4 per thread
#pragma unroll 4
        for (int d = 0; d < 64; d++) {
            float a[4];
#pragma unroll
            for (int i = 0; i < 4; i++) a[i] = Qp[ty * 4 + i][d];
            const float4 cv = *(const float4*)&Cs[d][tx * 4];
            float c[4] = {cv.x, cv.y, cv.z, cv.w};
#pragma unroll
            for (int i = 0; i < 4; i++)
#pragma unroll
                for (int j = 0; j < 4; j++) acc[i][j] += a[i] * c[j];
        }
        __syncthreads();
    }

    const float4 bv = *(const float4*)(b_out + tx * 4);
    const float bj[4] = {bv.x, bv.y, bv.z, bv.w};
#pragma unroll
    for (int i = 0; i < 4; i++) {
        float4 w = make_float4(acc[i][0] + bj[0], acc[i][1] + bj[1],
                               acc[i][2] + bj[2], acc[i][3] + bj[3]);
        *(float4*)(out + (size_t)(t0g + ty * 4 + i) * DD + tx * 4) = w;
    }
}

// ---------------------------------------------------------------------------
extern "C" void kernel_launch(void* const* d_in, const int* in_sizes, int n_in,
                              void* d_out, int out_size)
{
    const float* q  = (const float*)d_in[0];
    const float* k  = (const float*)d_in[1];
    const float* v  = (const float*)d_in[2];
    const float* W  = (const float*)d_in[3];
    const float* bo = (const float*)d_in[4];
    float* out = (float*)d_out;

    kv_partial_kernel<<<BH * CH, 256>>>(k, v);
    fold_kernel<<<BH, 256>>>(W);
    out_kernel<<<(BB * NN) / 64, 256>>>(q, bo, out);
}

// round 3
// speedup vs baseline: 1.6668x; 1.6668x over previous
#include <cuda_runtime.h>

#define BB 4
#define NN 4096
#define HH 16
#define DD 64
#define HD (HH*DD)          // 1024
#define BH (BB*HH)          // 64
#define CH 8                // chunks over N for phase-1 parallelism
#define CHTOK (NN/CH)       // 512 tokens per chunk
#define EPSZ 1e-6f

#define KVSTR 72            // Ks/Vs smem stride (==8 mod 32: conflict-free frags, rowvar 0..3)
#define QSTR  68            // Qp smem stride (==4 mod 32: conflict-free frags, rowvar 0..7)
#define CSTR  72            // Cs smem stride

// Scratch (static device globals — no allocation)
__device__ float g_KVpart[CH*BH*DD*DD];   // 8 MB: per-chunk partial K^T V
__device__ float g_KSpart[CH*BH*DD];
__device__ float g_C[BH*DD*DD];           // folded KV @ W_out_h^T
__device__ float g_Ksum[BH*DD];

__device__ __forceinline__ float phi(float x) { return x > 0.0f ? x + 1.0f : __expf(x); }

__device__ __forceinline__ float tf32r(float x) {
    unsigned u;
    asm("cvt.rna.tf32.f32 %0, %1;" : "=r"(u) : "f"(x));
    return __uint_as_float(u);
}
__device__ __forceinline__ float4 phi4r(float4 v) {
    float4 r;
    r.x = tf32r(phi(v.x)); r.y = tf32r(phi(v.y));
    r.z = tf32r(phi(v.z)); r.w = tf32r(phi(v.w));
    return r;
}
__device__ __forceinline__ float4 r4(float4 v) {
    float4 r;
    r.x = tf32r(v.x); r.y = tf32r(v.y); r.z = tf32r(v.z); r.w = tf32r(v.w);
    return r;
}

__device__ __forceinline__ void mma_tf32(float c[4],
    unsigned a0, unsigned a1, unsigned a2, unsigned a3,
    unsigned b0, unsigned b1)
{
    asm volatile(
        "mma.sync.aligned.m16n8k8.row.col.f32.tf32.tf32.f32 "
        "{%0,%1,%2,%3},{%4,%5,%6,%7},{%8,%9},{%0,%1,%2,%3};"
        : "+f"(c[0]), "+f"(c[1]), "+f"(c[2]), "+f"(c[3])
        : "r"(a0), "r"(a1), "r"(a2), "r"(a3), "r"(b0), "r"(b1));
}
__device__ __forceinline__ unsigned fb(float x) { return __float_as_uint(x); }

// ---------------------------------------------------------------------------
// Phase 1: partial KV[d][m] = sum_t phi(K[t][d]) * V[t][m]  via tf32 MMA.
// A[m=d][k=t] = Ks[t][d]  (read transposed from natural tile)
// B[k=t][n=m] = Vs[t][m]  (natural)
// 512 blocks x 256 threads (8 warps); warp tile = 16(d) x 32(m).
// ---------------------------------------------------------------------------
__global__ __launch_bounds__(256) void kv_partial_kernel(
    const float* __restrict__ key, const float* __restrict__ value)
{
    __shared__ float Ks[32][KVSTR];
    __shared__ float Vs[32][KVSTR];

    const int bx  = blockIdx.x;
    const int c   = bx % CH;
    const int bh  = bx / CH;
    const int b   = bh / HH;
    const int h   = bh % HH;
    const int tid = threadIdx.x;
    const int lane = tid & 31, warp = tid >> 5;
    const int dRow = (warp & 3) * 16;
    const int mCol = (warp >> 2) * 32;
    const int ar = lane >> 2;   // 0..7
    const int ac = lane & 3;    // 0..3

    float acc[4][4];
#pragma unroll
    for (int nt = 0; nt < 4; nt++)
#pragma unroll
        for (int j = 0; j < 4; j++) acc[nt][j] = 0.0f;
    float ksacc = 0.0f;

    const int n0 = c * CHTOK;

    for (int tile = 0; tile < CHTOK / 32; tile++) {
        const int t0 = n0 + tile * 32;
#pragma unroll
        for (int i = 0; i < 2; i++) {
            const int lin = tid + i * 256;
            const int t   = lin >> 4;
            const int d4  = (lin & 15) * 4;
            const int row = b * NN + t0 + t;
            const float4 kq = *(const float4*)(key   + (size_t)row * HD + h * DD + d4);
            const float4 vq = *(const float4*)(value + (size_t)row * HD + h * DD + d4);
            *(float4*)&Ks[t][d4] = phi4r(kq);
            *(float4*)&Vs[t][d4] = r4(vq);
        }
        __syncthreads();

        if (tid < 64) {
#pragma unroll
            for (int t = 0; t < 32; t++) ksacc += Ks[t][tid];
        }

#pragma unroll
        for (int kk = 0; kk < 4; kk++) {
            const int k0 = kk * 8;
            const unsigned a0 = fb(Ks[k0 + ac    ][dRow + ar    ]);
            const unsigned a1 = fb(Ks[k0 + ac    ][dRow + ar + 8]);
            const unsigned a2 = fb(Ks[k0 + ac + 4][dRow + ar    ]);
            const unsigned a3 = fb(Ks[k0 + ac + 4][dRow + ar + 8]);
#pragma unroll
            for (int nt = 0; nt < 4; nt++) {
                const int nc = mCol + nt * 8 + ar;
                const unsigned b0 = fb(Vs[k0 + ac    ][nc]);
                const unsigned b1 = fb(Vs[k0 + ac + 4][nc]);
                mma_tf32(acc[nt], a0, a1, a2, a3, b0, b1);
            }
        }
        __syncthreads();
    }

    float* outp = g_KVpart + (size_t)(c * BH + bh) * DD * DD;
#pragma unroll
    for (int nt = 0; nt < 4; nt++) {
        const int col = mCol + nt * 8 + 2 * ac;
        const int r0  = dRow + ar;
        *(float2*)(outp + r0 * DD + col)       = make_float2(acc[nt][0], acc[nt][1]);
        *(float2*)(outp + (r0 + 8) * DD + col) = make_float2(acc[nt][2], acc[nt][3]);
    }
    if (tid < 64) g_KSpart[(c * BH + bh) * DD + tid] = ksacc;
}

// ---------------------------------------------------------------------------
// Phase 1.5: reduce chunk partials; fold projection (fp32, tiny).
// ---------------------------------------------------------------------------
__global__ __launch_bounds__(256) void fold_kernel(const float* __restrict__ W_out)
{
    __shared__ float KVs[DD][68];
    __shared__ float Ws[DD][68];

    const int bh  = blockIdx.x;
    const int h   = bh % HH;
    const int tid = threadIdx.x;
    const int ty  = tid >> 4;
    const int tx  = tid & 15;

#pragma unroll
    for (int i = 0; i < 4; i++) {
        const int lin = (tid + i * 256) * 4;
        float4 s = make_float4(0.f, 0.f, 0.f, 0.f);
#pragma unroll
        for (int cc = 0; cc < CH; cc++) {
            const float4 p = *(const float4*)(g_KVpart + (size_t)(cc * BH + bh) * DD * DD + lin);
            s.x += p.x; s.y += p.y; s.z += p.z; s.w += p.w;
        }
        const int d = lin >> 6, m = lin & 63;
        *(float4*)&KVs[d][m] = s;
    }
#pragma unroll
    for (int i = 0; i < 4; i++) {
        const int lin = (tid + i * 256) * 4;
        const int j = lin >> 6, m = lin & 63;
        *(float4*)&Ws[j][m] = *(const float4*)(W_out + (size_t)j * HD + h * DD + m);
    }
    if (tid < 64) {
        float s = 0.0f;
#pragma unroll
        for (int cc = 0; cc < CH; cc++) s += g_KSpart[(cc * BH + bh) * DD + tid];
        g_Ksum[bh * DD + tid] = s;
    }
    __syncthreads();

    float acc[4][4];
#pragma unroll
    for (int i = 0; i < 4; i++)
#pragma unroll
        for (int j = 0; j < 4; j++) acc[i][j] = 0.0f;

#pragma unroll 4
    for (int m = 0; m < 64; m++) {
        float a[4], w[4];
#pragma unroll
        for (int i = 0; i < 4; i++) a[i] = KVs[ty * 4 + i][m];
#pragma unroll
        for (int j = 0; j < 4; j++) w[j] = Ws[tx * 4 + j][m];
#pragma unroll
        for (int i = 0; i < 4; i++)
#pragma unroll
            for (int j = 0; j < 4; j++) acc[i][j] += a[i] * w[j];
    }

    float* cp = g_C + (size_t)bh * DD * DD;
#pragma unroll
    for (int i = 0; i < 4; i++) {
        float4 w = make_float4(acc[i][0], acc[i][1], acc[i][2], acc[i][3]);
        *(float4*)(cp + (ty * 4 + i) * DD + tx * 4) = w;
    }
}

// ---------------------------------------------------------------------------
// Phase 2: out[t][j] = b[j] + sum_h Z[t,h] * (Qphi[t,h,:] @ C[b,h][:,j])
// A[m=t][k=d] = Qp[t][d] (natural), B[k=d][n=j] = Cs[d][j] (natural).
// 256 blocks x 256 threads; warp tile = 16(t) x 32(j), acc across heads.
// ---------------------------------------------------------------------------
__global__ __launch_bounds__(256) void out_kernel(
    const float* __restrict__ query, const float* __restrict__ b_out,
    float* __restrict__ out)
{
    __shared__ float Qp[64][QSTR];
    __shared__ float Cs[64][CSTR];
    __shared__ float Ksum_s[DD];

    const int blk = blockIdx.x;
    const int b   = blk / (NN / 64);
    const int t0g = blk * 64;
    const int tid = threadIdx.x;
    const int lane = tid & 31, warp = tid >> 5;
    const int tRow = (warp & 3) * 16;
    const int jCol = (warp >> 2) * 32;
    const int ar = lane >> 2;
    const int ac = lane & 3;

    float acc[4][4];
#pragma unroll
    for (int nt = 0; nt < 4; nt++)
#pragma unroll
        for (int j = 0; j < 4; j++) acc[nt][j] = 0.0f;

    for (int h = 0; h < HH; h++) {
        const int bh = b * HH + h;
        if (tid < 64) Ksum_s[tid] = g_Ksum[bh * DD + tid];

#pragma unroll
        for (int i = 0; i < 4; i++) {
            const int lin = tid + i * 256;
            const int t  = lin >> 4;
            const int d4 = (lin & 15) * 4;
            const float4 qv = *(const float4*)(query + (size_t)(t0g + t) * HD + h * DD + d4);
            *(float4*)&Qp[t][d4] = phi4r(qv);
            *(float4*)&Cs[t][d4] = r4(*(const float4*)(g_C + (size_t)bh * DD * DD + lin * 4));
        }
        __syncthreads();

        if (tid < 64) {
            float dot = 0.0f;
#pragma unroll
            for (int d = 0; d < 64; d++) dot += Qp[tid][d] * Ksum_s[d];
            const float z = 1.0f / (dot + EPSZ);
#pragma unroll
            for (int d = 0; d < 64; d++) Qp[tid][d] = tf32r(Qp[tid][d] * z);
        }
        __syncthreads();

#pragma unroll
        for (int kk = 0; kk < 8; kk++) {
            const int k0 = kk * 8;
            const unsigned a0 = fb(Qp[tRow + ar    ][k0 + ac    ]);
            const unsigned a1 = fb(Qp[tRow + ar + 8][k0 + ac    ]);
            const unsigned a2 = fb(Qp[tRow + ar    ][k0 + ac + 4]);
            const unsigned a3 = fb(Qp[tRow + ar + 8][k0 + ac + 4]);
#pragma unroll
            for (int nt = 0; nt < 4; nt++) {
                const int nc = jCol + nt * 8 + ar;
                const unsigned b0 = fb(Cs[k0 + ac    ][nc]);
                const unsigned b1 = fb(Cs[k0 + ac + 4][nc]);
                mma_tf32(acc[nt], a0, a1, a2, a3, b0, b1);
            }
        }
        __syncthreads();
    }

#pragma unroll
    for (int nt = 0; nt < 4; nt++) {
        const int col = jCol + nt * 8 + 2 * ac;
        const float bj0 = b_out[col], bj1 = b_out[col + 1];
        const int r0 = t0g + tRow + ar;
        *(float2*)(out + (size_t)r0 * DD + col) =
            make_float2(acc[nt][0] + bj0, acc[nt][1] + bj1);
        *(float2*)(out + (size_t)(r0 + 8) * DD + col) =
            make_float2(acc[nt][2] + bj0, acc[nt][3] + bj1);
    }
}

// ---------------------------------------------------------------------------
extern "C" void kernel_launch(void* const* d_in, const int* in_sizes, int n_in,
                              void* d_out, int out_size)
{
    const float* q  = (const float*)d_in[0];
    const float* k  = (const float*)d_in[1];
    const float* v  = (const float*)d_in[2];
    const float* W  = (const float*)d_in[3];
    const float* bo = (const float*)d_in[4];
    float* out = (float*)d_out;

    kv_partial_kernel<<<BH * CH, 256>>>(k, v);
    fold_kernel<<<BH, 256>>>(W);
    out_kernel<<<(BB * NN) / 64, 256>>>(q, bo, out);
}

// round 4
// speedup vs baseline: 1.9180x; 1.1507x over previous
#include <cuda_runtime.h>

#define BB 4
#define NN 4096
#define HH 16
#define DD 64
#define HD (HH*DD)          // 1024
#define BH (BB*HH)          // 64
#define CH 8
#define CHTOK (NN/CH)       // 512
#define EPSZ 1e-6f

#define KVSTR 72            // ==8 mod 32: conflict-free frags (rowvar 0..3)
#define QSTR  68            // ==4 mod 32: conflict-free frags (rowvar 0..7)
#define CSTR  72

__device__ float g_KVpart[CH*BH*DD*DD];
__device__ float g_KSpart[CH*BH*DD];
__device__ float g_C[BH*DD*DD];
__device__ float g_Ksum[BH*DD];

__device__ __forceinline__ float phi(float x) { return x > 0.0f ? x + 1.0f : __expf(x); }

__device__ __forceinline__ float tf32r(float x) {
    unsigned u;
    asm("cvt.rna.tf32.f32 %0, %1;" : "=r"(u) : "f"(x));
    return __uint_as_float(u);
}
__device__ __forceinline__ float4 phi4(float4 v) {
    float4 r; r.x = phi(v.x); r.y = phi(v.y); r.z = phi(v.z); r.w = phi(v.w);
    return r;
}
__device__ __forceinline__ float4 r4(float4 v) {
    float4 r; r.x = tf32r(v.x); r.y = tf32r(v.y); r.z = tf32r(v.z); r.w = tf32r(v.w);
    return r;
}

__device__ __forceinline__ void mma_tf32(float c[4],
    unsigned a0, unsigned a1, unsigned a2, unsigned a3,
    unsigned b0, unsigned b1)
{
    asm volatile(
        "mma.sync.aligned.m16n8k8.row.col.f32.tf32.tf32.f32 "
        "{%0,%1,%2,%3},{%4,%5,%6,%7},{%8,%9},{%0,%1,%2,%3};"
        : "+f"(c[0]), "+f"(c[1]), "+f"(c[2]), "+f"(c[3])
        : "r"(a0), "r"(a1), "r"(a2), "r"(a3), "r"(b0), "r"(b1));
}
__device__ __forceinline__ unsigned fb(float x) { return __float_as_uint(x); }
__device__ __forceinline__ unsigned phit(float x) { return fb(tf32r(phi(x))); }

__device__ __forceinline__ void cpa16(void* smem, const void* g) {
    unsigned s = (unsigned)__cvta_generic_to_shared(smem);
    asm volatile("cp.async.ca.shared.global [%0], [%1], 16;" :: "r"(s), "l"(g));
}
#define CP_COMMIT() asm volatile("cp.async.commit_group;")
#define CP_WAIT(n)  asm volatile("cp.async.wait_group %0;" :: "n"(n))

// ---------------------------------------------------------------------------
// Phase 1: partial KV[d][m] = sum_t phi(K[t][d]) * V[t][m], tf32 MMA,
// 2-stage cp.async pipeline over 32-token tiles. 512 blocks x 256 threads.
// ---------------------------------------------------------------------------
__global__ __launch_bounds__(256) void kv_partial_kernel(
    const float* __restrict__ key, const float* __restrict__ value)
{
    __shared__ float Ks[2][32][KVSTR];
    __shared__ float Vs[2][32][KVSTR];
    __shared__ float kpart[4][64];

    const int bx  = blockIdx.x;
    const int c   = bx % CH;
    const int bh  = bx / CH;
    const int b   = bh / HH;
    const int h   = bh % HH;
    const int tid = threadIdx.x;
    const int lane = tid & 31, warp = tid >> 5;
    const int dRow = (warp & 3) * 16;
    const int mCol = (warp >> 2) * 32;
    const int ar = lane >> 2;
    const int ac = lane & 3;

    // cp.async chunk assignment: 2 chunks per tensor per thread
    const int t0i = tid >> 4;        // 0..15
    const int t1i = t0i + 16;        // 16..31
    const int d4  = (tid & 15) * 4;

    const int n0 = c * CHTOK;
    const size_t gbase = (size_t)(b * NN + n0) * HD + h * DD + d4;
    const float* kp0 = key   + gbase + (size_t)t0i * HD;
    const float* kp1 = key   + gbase + (size_t)t1i * HD;
    const float* vp0 = value + gbase + (size_t)t0i * HD;
    const float* vp1 = value + gbase + (size_t)t1i * HD;

    float acc[4][4];
#pragma unroll
    for (int nt = 0; nt < 4; nt++)
#pragma unroll
        for (int j = 0; j < 4; j++) acc[nt][j] = 0.0f;

    const int kq = tid >> 6;         // Ksum quarter 0..3
    const int kcol = tid & 63;
    float ksacc = 0.0f;

    // prologue: tile 0 into stage 0
    {
        cpa16(&Ks[0][t0i][d4], kp0);
        cpa16(&Ks[0][t1i][d4], kp1);
        cpa16(&Vs[0][t0i][d4], vp0);
        cpa16(&Vs[0][t1i][d4], vp1);
        CP_COMMIT();
    }

    for (int tile = 0; tile < CHTOK / 32; tile++) {
        const int cur = tile & 1;
        if (tile < CHTOK / 32 - 1) {
            const size_t off = (size_t)(tile + 1) * 32 * HD;
            const int nxt = cur ^ 1;
            cpa16(&Ks[nxt][t0i][d4], kp0 + off);
            cpa16(&Ks[nxt][t1i][d4], kp1 + off);
            cpa16(&Vs[nxt][t0i][d4], vp0 + off);
            cpa16(&Vs[nxt][t1i][d4], vp1 + off);
            CP_COMMIT();
            CP_WAIT(1);
        } else {
            CP_WAIT(0);
        }
        __syncthreads();

        // Ksum partial: 8 rows per thread
#pragma unroll
        for (int tt = 0; tt < 8; tt++)
            ksacc += phi(Ks[cur][kq * 8 + tt][kcol]);

#pragma unroll
        for (int kk = 0; kk < 4; kk++) {
            const int k0 = kk * 8;
            const unsigned a0 = phit(Ks[cur][k0 + ac    ][dRow + ar    ]);
            const unsigned a1 = phit(Ks[cur][k0 + ac    ][dRow + ar + 8]);
            const unsigned a2 = phit(Ks[cur][k0 + ac + 4][dRow + ar    ]);
            const unsigned a3 = phit(Ks[cur][k0 + ac + 4][dRow + ar + 8]);
#pragma unroll
            for (int nt = 0; nt < 4; nt++) {
                const int nc = mCol + nt * 8 + ar;
                const unsigned b0 = fb(tf32r(Vs[cur][k0 + ac    ][nc]));
                const unsigned b1 = fb(tf32r(Vs[cur][k0 + ac + 4][nc]));
                mma_tf32(acc[nt], a0, a1, a2, a3, b0, b1);
            }
        }
        __syncthreads();
    }

    kpart[kq][kcol] = ksacc;
    __syncthreads();
    if (tid < 64)
        g_KSpart[(c * BH + bh) * DD + tid] =
            kpart[0][tid] + kpart[1][tid] + kpart[2][tid] + kpart[3][tid];

    float* outp = g_KVpart + (size_t)(c * BH + bh) * DD * DD;
#pragma unroll
    for (int nt = 0; nt < 4; nt++) {
        const int col = mCol + nt * 8 + 2 * ac;
        const int r0  = dRow + ar;
        *(float2*)(outp + r0 * DD + col)       = make_float2(acc[nt][0], acc[nt][1]);
        *(float2*)(outp + (r0 + 8) * DD + col) = make_float2(acc[nt][2], acc[nt][3]);
    }
}

// ---------------------------------------------------------------------------
// Phase 1.5: reduce chunk partials; fold projection (fp32, tiny).
// ---------------------------------------------------------------------------
__global__ __launch_bounds__(256) void fold_kernel(const float* __restrict__ W_out)
{
    __shared__ float KVs[DD][68];
    __shared__ float Ws[DD][68];

    const int bh  = blockIdx.x;
    const int h   = bh % HH;
    const int tid = threadIdx.x;
    const int ty  = tid >> 4;
    const int tx  = tid & 15;

#pragma unroll
    for (int i = 0; i < 4; i++) {
        const int lin = (tid + i * 256) * 4;
        float4 s = make_float4(0.f, 0.f, 0.f, 0.f);
#pragma unroll
        for (int cc = 0; cc < CH; cc++) {
            const float4 p = *(const float4*)(g_KVpart + (size_t)(cc * BH + bh) * DD * DD + lin);
            s.x += p.x; s.y += p.y; s.z += p.z; s.w += p.w;
        }
        const int d = lin >> 6, m = lin & 63;
        *(float4*)&KVs[d][m] = s;
    }
#pragma unroll
    for (int i = 0; i < 4; i++) {
        const int lin = (tid + i * 256) * 4;
        const int j = lin >> 6, m = lin & 63;
        *(float4*)&Ws[j][m] = *(const float4*)(W_out + (size_t)j * HD + h * DD + m);
    }
    if (tid < 64) {
        float s = 0.0f;
#pragma unroll
        for (int cc = 0; cc < CH; cc++) s += g_KSpart[(cc * BH + bh) * DD + tid];
        g_Ksum[bh * DD + tid] = s;
    }
    __syncthreads();

    float acc[4][4];
#pragma unroll
    for (int i = 0; i < 4; i++)
#pragma unroll
        for (int j = 0; j < 4; j++) acc[i][j] = 0.0f;

#pragma unroll 4
    for (int m = 0; m < 64; m++) {
        float a[4], w[4];
#pragma unroll
        for (int i = 0; i < 4; i++) a[i] = KVs[ty * 4 + i][m];
#pragma unroll
        for (int j = 0; j < 4; j++) w[j] = Ws[tx * 4 + j][m];
#pragma unroll
        for (int i = 0; i < 4; i++)
#pragma unroll
            for (int j = 0; j < 4; j++) acc[i][j] += a[i] * w[j];
    }

    float* cp = g_C + (size_t)bh * DD * DD;
#pragma unroll
    for (int i = 0; i < 4; i++) {
        float4 w = make_float4(acc[i][0], acc[i][1], acc[i][2], acc[i][3]);
        *(float4*)(cp + (ty * 4 + i) * DD + tx * 4) = w;
    }
}

// ---------------------------------------------------------------------------
// Phase 2: out[t][j] = b[j] + sum_h Z[t,h] * (Qphi[t,h,:] @ C[b,h][:,j])
// Z applied AFTER the per-head MMA (each thread owns 2 rows -> 2 scalars).
// Per-token dot computed from registers in the store phase (shfl reduce).
// Next head's Q/C/Ksum prefetched into registers during MMA.
// ---------------------------------------------------------------------------
__global__ __launch_bounds__(256) void out_kernel(
    const float* __restrict__ query, const float* __restrict__ b_out,
    float* __restrict__ out)
{
    __shared__ float Qp[64][QSTR];
    __shared__ float Cs[64][CSTR];
    __shared__ float dsum[64];

    const int blk = blockIdx.x;
    const int b   = blk / (NN / 64);
    const int t0g = blk * 64;
    const int tid = threadIdx.x;
    const int lane = tid & 31, warp = tid >> 5;
    const int tRow = (warp & 3) * 16;
    const int jCol = (warp >> 2) * 32;
    const int ar = lane >> 2;
    const int ac = lane & 3;

    // chunk ids: tokens ct+16i, dims cd4..cd4+3
    const int ct  = tid >> 4;        // 0..15
    const int cd4 = (tid & 15) * 4;

    const float* qbase = query + (size_t)(t0g + ct) * HD + cd4;
    const float* cbase = g_C + (size_t)(b * HH) * DD * DD + ct * 64 + cd4;
    const float* kbase = g_Ksum + (b * HH) * DD + cd4;

    float acc[4][4];
#pragma unroll
    for (int nt = 0; nt < 4; nt++)
#pragma unroll
        for (int j = 0; j < 4; j++) acc[nt][j] = 0.0f;

    float4 qbuf[4], cbuf[4], ksv;
    // prologue: head 0
#pragma unroll
    for (int i = 0; i < 4; i++) {
        qbuf[i] = *(const float4*)(qbase + (size_t)i * 16 * HD);
        cbuf[i] = *(const float4*)(cbase + i * 16 * 64);
    }
    ksv = *(const float4*)(kbase);

    for (int h = 0; h < HH; h++) {
        // ---- store phase: phi+cvt Q, cvt C, per-token dot via shfl ----
#pragma unroll
        for (int i = 0; i < 4; i++) {
            const int t = ct + i * 16;
            const float4 praw = phi4(qbuf[i]);
            *(float4*)&Qp[t][cd4] = r4(praw);
            *(float4*)&Cs[t][cd4] = r4(cbuf[i]);
            float partial = praw.x * ksv.x + praw.y * ksv.y +
                            praw.z * ksv.z + praw.w * ksv.w;
#pragma unroll
            for (int off = 8; off >= 1; off >>= 1)
                partial += __shfl_xor_sync(0xffffffffu, partial, off);
            if ((lane & 15) == 0) dsum[t] = partial;
        }
        __syncthreads();

        // ---- prefetch next head during MMA ----
        if (h < HH - 1) {
#pragma unroll
            for (int i = 0; i < 4; i++) {
                qbuf[i] = *(const float4*)(qbase + (h + 1) * DD + (size_t)i * 16 * HD);
                cbuf[i] = *(const float4*)(cbase + (h + 1) * DD * DD + i * 16 * 64);
            }
            ksv = *(const float4*)(kbase + (h + 1) * DD);
        }

        // ---- MMA into temp accumulator ----
        float tacc[4][4];
#pragma unroll
        for (int nt = 0; nt < 4; nt++)
#pragma unroll
            for (int j = 0; j < 4; j++) tacc[nt][j] = 0.0f;

#pragma unroll
        for (int kk = 0; kk < 8; kk++) {
            const int k0 = kk * 8;
            const unsigned a0 = fb(Qp[tRow + ar    ][k0 + ac    ]);
            const unsigned a1 = fb(Qp[tRow + ar + 8][k0 + ac    ]);
            const unsigned a2 = fb(Qp[tRow + ar    ][k0 + ac + 4]);
            const unsigned a3 = fb(Qp[tRow + ar + 8][k0 + ac + 4]);
#pragma unroll
            for (int nt = 0; nt < 4; nt++) {
                const int nc = jCol + nt * 8 + ar;
                const unsigned b0 = fb(Cs[k0 + ac    ][nc]);
                const unsigned b1 = fb(Cs[k0 + ac + 4][nc]);
                mma_tf32(tacc[nt], a0, a1, a2, a3, b0, b1);
            }
        }

        // ---- Z scale-accumulate (2 rows per thread) ----
        const float z0 = 1.0f / (dsum[tRow + ar    ] + EPSZ);
        const float z1 = 1.0f / (dsum[tRow + ar + 8] + EPSZ);
#pragma unroll
        for (int nt = 0; nt < 4; nt++) {
            acc[nt][0] += z0 * tacc[nt][0];
            acc[nt][1] += z0 * tacc[nt][1];
            acc[nt][2] += z1 * tacc[nt][2];
            acc[nt][3] += z1 * tacc[nt][3];
        }
        __syncthreads();
    }

#pragma unroll
    for (int nt = 0; nt < 4; nt++) {
        const int col = jCol + nt * 8 + 2 * ac;
        const float bj0 = b_out[col], bj1 = b_out[col + 1];
        const int r0 = t0g + tRow + ar;
        *(float2*)(out + (size_t)r0 * DD + col) =
            make_float2(acc[nt][0] + bj0, acc[nt][1] + bj1);
        *(float2*)(out + (size_t)(r0 + 8) * DD + col) =
            make_float2(acc[nt][2] + bj0, acc[nt][3] + bj1);
    }
}

// ---------------------------------------------------------------------------
extern "C" void kernel_launch(void* const* d_in, const int* in_sizes, int n_in,
                              void* d_out, int out_size)
{
    const float* q  = (const float*)d_in[0];
    const float* k  = (const float*)d_in[1];
    const float* v  = (const float*)d_in[2];
    const float* W  = (const float*)d_in[3];
    const float* bo = (const float*)d_in[4];
    float* out = (float*)d_out;

    kv_partial_kernel<<<BH * CH, 256>>>(k, v);
    fold_kernel<<<BH, 256>>>(W);
    out_kernel<<<(BB * NN) / 64, 256>>>(q, bo, out);
}

// round 5
// speedup vs baseline: 1.9837x; 1.0343x over previous
#include <cuda_runtime.h>

#define BB 4
#define NN 4096
#define HH 16
#define DD 64
#define HD (HH*DD)          // 1024
#define BH (BB*HH)          // 64
#define CH 16
#define CHTOK (NN/CH)       // 256
#define EPSZ 1e-6f

#define KVSTR 72            // ==8 mod 32: conflict-free frags (rowvar 0..7 via 8ac+ar)
#define QSTR  68            // ==4 mod 32: conflict-free frags (4ar+ac)
#define CSTR  72

__device__ float g_KVpart[CH*BH*DD*DD];   // 16 MB
__device__ float g_KSpart[CH*BH*DD];
__device__ float g_C[BH*DD*DD];
__device__ float g_Ksum[BH*DD];

__device__ __forceinline__ float phi(float x) { return x > 0.0f ? x + 1.0f : __expf(x); }

__device__ __forceinline__ float tf32r(float x) {
    unsigned u;
    asm("cvt.rna.tf32.f32 %0, %1;" : "=r"(u) : "f"(x));
    return __uint_as_float(u);
}
__device__ __forceinline__ float4 phi4(float4 v) {
    float4 r; r.x = phi(v.x); r.y = phi(v.y); r.z = phi(v.z); r.w = phi(v.w);
    return r;
}
__device__ __forceinline__ float4 r4(float4 v) {
    float4 r; r.x = tf32r(v.x); r.y = tf32r(v.y); r.z = tf32r(v.z); r.w = tf32r(v.w);
    return r;
}

__device__ __forceinline__ void mma_tf32(float c[4],
    unsigned a0, unsigned a1, unsigned a2, unsigned a3,
    unsigned b0, unsigned b1)
{
    asm volatile(
        "mma.sync.aligned.m16n8k8.row.col.f32.tf32.tf32.f32 "
        "{%0,%1,%2,%3},{%4,%5,%6,%7},{%8,%9},{%0,%1,%2,%3};"
        : "+f"(c[0]), "+f"(c[1]), "+f"(c[2]), "+f"(c[3])
        : "r"(a0), "r"(a1), "r"(a2), "r"(a3), "r"(b0), "r"(b1));
}
__device__ __forceinline__ unsigned fb(float x) { return __float_as_uint(x); }

__device__ __forceinline__ void cpa16(void* smem, const void* g) {
    unsigned s = (unsigned)__cvta_generic_to_shared(smem);
    asm volatile("cp.async.ca.shared.global [%0], [%1], 16;" :: "r"(s), "l"(g));
}
#define CP_COMMIT() asm volatile("cp.async.commit_group;")
#define CP_WAIT(n)  asm volatile("cp.async.wait_group %0;" :: "n"(n))

// ---------------------------------------------------------------------------
// Phase 1: partial KV[d][m] = sum_t phi(K[t][d]) * V[t][m], tf32 MMA.
// 2-stage cp.async pipeline; phi/cvt applied ONCE per element via smem RMW
// (each thread converts exactly the chunks it copied — visible after wait).
// 1024 blocks x 256 threads.
// ---------------------------------------------------------------------------
__global__ __launch_bounds__(256) void kv_partial_kernel(
    const float* __restrict__ key, const float* __restrict__ value)
{
    __shared__ float Ks[2][32][KVSTR];
    __shared__ float Vs[2][32][KVSTR];
    __shared__ float kpart[4][64];

    const int bx  = blockIdx.x;
    const int c   = bx % CH;
    const int bh  = bx / CH;
    const int b   = bh / HH;
    const int h   = bh % HH;
    const int tid = threadIdx.x;
    const int lane = tid & 31, warp = tid >> 5;
    const int dRow = (warp & 3) * 16;
    const int mCol = (warp >> 2) * 32;
    const int ar = lane >> 2;
    const int ac = lane & 3;

    const int t0i = tid >> 4;        // 0..15
    const int t1i = t0i + 16;
    const int d4  = (tid & 15) * 4;

    const int n0 = c * CHTOK;
    const size_t gbase = (size_t)(b * NN + n0) * HD + h * DD + d4;
    const float* kp0 = key   + gbase + (size_t)t0i * HD;
    const float* kp1 = key   + gbase + (size_t)t1i * HD;
    const float* vp0 = value + gbase + (size_t)t0i * HD;
    const float* vp1 = value + gbase + (size_t)t1i * HD;

    float acc[4][4];
#pragma unroll
    for (int nt = 0; nt < 4; nt++)
#pragma unroll
        for (int j = 0; j < 4; j++) acc[nt][j] = 0.0f;

    const int kq = tid >> 6;
    const int kcol = tid & 63;
    float ksacc = 0.0f;

    // prologue: tile 0 -> stage 0
    cpa16(&Ks[0][t0i][d4], kp0);
    cpa16(&Ks[0][t1i][d4], kp1);
    cpa16(&Vs[0][t0i][d4], vp0);
    cpa16(&Vs[0][t1i][d4], vp1);
    CP_COMMIT();

    for (int tile = 0; tile < CHTOK / 32; tile++) {
        const int cur = tile & 1;
        if (tile < CHTOK / 32 - 1) {
            const size_t off = (size_t)(tile + 1) * 32 * HD;
            const int nxt = cur ^ 1;
            cpa16(&Ks[nxt][t0i][d4], kp0 + off);
            cpa16(&Ks[nxt][t1i][d4], kp1 + off);
            cpa16(&Vs[nxt][t0i][d4], vp0 + off);
            cpa16(&Vs[nxt][t1i][d4], vp1 + off);
            CP_COMMIT();
            CP_WAIT(1);
        } else {
            CP_WAIT(0);
        }

        // RMW convert own chunks (once per element)
        *(float4*)&Ks[cur][t0i][d4] = r4(phi4(*(const float4*)&Ks[cur][t0i][d4]));
        *(float4*)&Ks[cur][t1i][d4] = r4(phi4(*(const float4*)&Ks[cur][t1i][d4]));
        *(float4*)&Vs[cur][t0i][d4] = r4(*(const float4*)&Vs[cur][t0i][d4]);
        *(float4*)&Vs[cur][t1i][d4] = r4(*(const float4*)&Vs[cur][t1i][d4]);
        __syncthreads();

#pragma unroll
        for (int tt = 0; tt < 8; tt++)
            ksacc += Ks[cur][kq * 8 + tt][kcol];

#pragma unroll
        for (int kk = 0; kk < 4; kk++) {
            const int k0 = kk * 8;
            const unsigned a0 = fb(Ks[cur][k0 + ac    ][dRow + ar    ]);
            const unsigned a1 = fb(Ks[cur][k0 + ac    ][dRow + ar + 8]);
            const unsigned a2 = fb(Ks[cur][k0 + ac + 4][dRow + ar    ]);
            const unsigned a3 = fb(Ks[cur][k0 + ac + 4][dRow + ar + 8]);
#pragma unroll
            for (int nt = 0; nt < 4; nt++) {
                const int nc = mCol + nt * 8 + ar;
                const unsigned b0 = fb(Vs[cur][k0 + ac    ][nc]);
                const unsigned b1 = fb(Vs[cur][k0 + ac + 4][nc]);
                mma_tf32(acc[nt], a0, a1, a2, a3, b0, b1);
            }
        }
        __syncthreads();
    }

    kpart[kq][kcol] = ksacc;
    __syncthreads();
    if (tid < 64)
        g_KSpart[(c * BH + bh) * DD + tid] =
            kpart[0][tid] + kpart[1][tid] + kpart[2][tid] + kpart[3][tid];

    float* outp = g_KVpart + (size_t)(c * BH + bh) * DD * DD;
#pragma unroll
    for (int nt = 0; nt < 4; nt++) {
        const int col = mCol + nt * 8 + 2 * ac;
        const int r0  = dRow + ar;
        *(float2*)(outp + r0 * DD + col)       = make_float2(acc[nt][0], acc[nt][1]);
        *(float2*)(outp + (r0 + 8) * DD + col) = make_float2(acc[nt][2], acc[nt][3]);
    }
}

// ---------------------------------------------------------------------------
// Phase 1.5: reduce chunk partials; fold projection (fp32, tiny).
// ---------------------------------------------------------------------------
__global__ __launch_bounds__(256) void fold_kernel(const float* __restrict__ W_out)
{
    __shared__ float KVs[DD][68];
    __shared__ float Ws[DD][68];

    const int bh  = blockIdx.x;
    const int h   = bh % HH;
    const int tid = threadIdx.x;
    const int ty  = tid >> 4;
    const int tx  = tid & 15;

#pragma unroll
    for (int i = 0; i < 4; i++) {
        const int lin = (tid + i * 256) * 4;
        float4 s = make_float4(0.f, 0.f, 0.f, 0.f);
#pragma unroll
        for (int cc = 0; cc < CH; cc++) {
            const float4 p = *(const float4*)(g_KVpart + (size_t)(cc * BH + bh) * DD * DD + lin);
            s.x += p.x; s.y += p.y; s.z += p.z; s.w += p.w;
        }
        const int d = lin >> 6, m = lin & 63;
        *(float4*)&KVs[d][m] = s;
    }
#pragma unroll
    for (int i = 0; i < 4; i++) {
        const int lin = (tid + i * 256) * 4;
        const int j = lin >> 6, m = lin & 63;
        *(float4*)&Ws[j][m] = *(const float4*)(W_out + (size_t)j * HD + h * DD + m);
    }
    if (tid < 64) {
        float s = 0.0f;
#pragma unroll
        for (int cc = 0; cc < CH; cc++) s += g_KSpart[(cc * BH + bh) * DD + tid];
        g_Ksum[bh * DD + tid] = s;
    }
    __syncthreads();

    float acc[4][4];
#pragma unroll
    for (int i = 0; i < 4; i++)
#pragma unroll
        for (int j = 0; j < 4; j++) acc[i][j] = 0.0f;

#pragma unroll 4
    for (int m = 0; m < 64; m++) {
        float a[4], w[4];
#pragma unroll
        for (int i = 0; i < 4; i++) a[i] = KVs[ty * 4 + i][m];
#pragma unroll
        for (int j = 0; j < 4; j++) w[j] = Ws[tx * 4 + j][m];
#pragma unroll
        for (int i = 0; i < 4; i++)
#pragma unroll
            for (int j = 0; j < 4; j++) acc[i][j] += a[i] * w[j];
    }

    float* cp = g_C + (size_t)bh * DD * DD;
#pragma unroll
    for (int i = 0; i < 4; i++) {
        float4 w = make_float4(acc[i][0], acc[i][1], acc[i][2], acc[i][3]);
        *(float4*)(cp + (ty * 4 + i) * DD + tx * 4) = w;
    }
}

// ---------------------------------------------------------------------------
// Phase 2: out[t][j] = b[j] + sum_h Z[t,h] * (Qphi[t,h,:] @ C[b,h][:,j])
// 512 threads (16 warps, 4x4 warp grid, 16x16 warp tiles). Z applied after
// the per-head MMA; per-token dot from registers via shfl; next head
// prefetched into registers during MMA. 256 blocks.
// ---------------------------------------------------------------------------
__global__ __launch_bounds__(512) void out_kernel(
    const float* __restrict__ query, const float* __restrict__ b_out,
    float* __restrict__ out)
{
    __shared__ float Qp[64][QSTR];
    __shared__ float Cs[64][CSTR];
    __shared__ float dsum[64];

    const int blk = blockIdx.x;
    const int b   = blk / (NN / 64);
    const int t0g = blk * 64;
    const int tid = threadIdx.x;
    const int lane = tid & 31, warp = tid >> 5;
    const int tRow = (warp >> 2) * 16;
    const int jCol = (warp & 3) * 16;
    const int ar = lane >> 2;
    const int ac = lane & 3;

    const int ct  = tid >> 4;        // 0..31
    const int cd4 = (tid & 15) * 4;

    const float* qbase = query + (size_t)(t0g + ct) * HD + cd4;
    const float* cbase = g_C + (size_t)(b * HH) * DD * DD + ct * 64 + cd4;
    const float* kbase = g_Ksum + (b * HH) * DD + cd4;

    float acc[2][4];
#pragma unroll
    for (int nt = 0; nt < 2; nt++)
#pragma unroll
        for (int j = 0; j < 4; j++) acc[nt][j] = 0.0f;

    float4 qbuf[2], cbuf[2], ksv;
#pragma unroll
    for (int i = 0; i < 2; i++) {
        qbuf[i] = *(const float4*)(qbase + (size_t)i * 32 * HD);
        cbuf[i] = *(const float4*)(cbase + i * 32 * 64);
    }
    ksv = *(const float4*)(kbase);

    for (int h = 0; h < HH; h++) {
        // store phase: phi+cvt Q, cvt C, per-token dot via shfl
#pragma unroll
        for (int i = 0; i < 2; i++) {
            const int t = ct + i * 32;
            const float4 praw = phi4(qbuf[i]);
            *(float4*)&Qp[t][cd4] = r4(praw);
            *(float4*)&Cs[t][cd4] = r4(cbuf[i]);
            float partial = praw.x * ksv.x + praw.y * ksv.y +
                            praw.z * ksv.z + praw.w * ksv.w;
#pragma unroll
            for (int off = 8; off >= 1; off >>= 1)
                partial += __shfl_xor_sync(0xffffffffu, partial, off);
            if ((lane & 15) == 0) dsum[t] = partial;
        }
        __syncthreads();

        // prefetch next head during MMA
        if (h < HH - 1) {
#pragma unroll
            for (int i = 0; i < 2; i++) {
                qbuf[i] = *(const float4*)(qbase + (h + 1) * DD + (size_t)i * 32 * HD);
                cbuf[i] = *(const float4*)(cbase + (size_t)(h + 1) * DD * DD + i * 32 * 64);
            }
            ksv = *(const float4*)(kbase + (h + 1) * DD);
        }

        float tacc[2][4];
#pragma unroll
        for (int nt = 0; nt < 2; nt++)
#pragma unroll
            for (int j = 0; j < 4; j++) tacc[nt][j] = 0.0f;

#pragma unroll
        for (int kk = 0; kk < 8; kk++) {
            const int k0 = kk * 8;
            const unsigned a0 = fb(Qp[tRow + ar    ][k0 + ac    ]);
            const unsigned a1 = fb(Qp[tRow + ar + 8][k0 + ac    ]);
            const unsigned a2 = fb(Qp[tRow + ar    ][k0 + ac + 4]);
            const unsigned a3 = fb(Qp[tRow + ar + 8][k0 + ac + 4]);
#pragma unroll
            for (int nt = 0; nt < 2; nt++) {
                const int nc = jCol + nt * 8 + ar;
                const unsigned b0 = fb(Cs[k0 + ac    ][nc]);
                const unsigned b1 = fb(Cs[k0 + ac + 4][nc]);
                mma_tf32(tacc[nt], a0, a1, a2, a3, b0, b1);
            }
        }

        const float z0 = 1.0f / (dsum[tRow + ar    ] + EPSZ);
        const float z1 = 1.0f / (dsum[tRow + ar + 8] + EPSZ);
#pragma unroll
        for (int nt = 0; nt < 2; nt++) {
            acc[nt][0] += z0 * tacc[nt][0];
            acc[nt][1] += z0 * tacc[nt][1];
            acc[nt][2] += z1 * tacc[nt][2];
            acc[nt][3] += z1 * tacc[nt][3];
        }
        __syncthreads();
    }

#pragma unroll
    for (int nt = 0; nt < 2; nt++) {
        const int col = jCol + nt * 8 + 2 * ac;
        const float bj0 = b_out[col], bj1 = b_out[col + 1];
        const int r0 = t0g + tRow + ar;
        *(float2*)(out + (size_t)r0 * DD + col) =
            make_float2(acc[nt][0] + bj0, acc[nt][1] + bj1);
        *(float2*)(out + (size_t)(r0 + 8) * DD + col) =
            make_float2(acc[nt][2] + bj0, acc[nt][3] + bj1);
    }
}

// ---------------------------------------------------------------------------
extern "C" void kernel_launch(void* const* d_in, const int* in_sizes, int n_in,
                              void* d_out, int out_size)
{
    const float* q  = (const float*)d_in[0];
    const float* k  = (const float*)d_in[1];
    const float* v  = (const float*)d_in[2];
    const float* W  = (const float*)d_in[3];
    const float* bo = (const float*)d_in[4];
    float* out = (float*)d_out;

    kv_partial_kernel<<<BH * CH, 256>>>(k, v);
    fold_kernel<<<BH, 256>>>(W);
    out_kernel<<<(BB * NN) / 64, 512>>>(q, bo, out);
}